// round 2
// baseline (speedup 1.0000x reference)
#include <cuda_runtime.h>

// PhysicsEngine: B=8, NL=128, NP=8192 pairwise soft-core energy -> 3 scalars/batch.
// Single fused kernel: grid (128 chunks, 8 batches) x 128 threads (thread = ligand),
// 64 SMEM-staged protein atoms per chunk. Last block (threadfence+atomic counter)
// reduces all partials and writes the 24 outputs. Deterministic, graph-capturable.

#define NB 8
#define NL 128
#define NP 8192
#define CHUNK 64
#define NCHUNK (NP / CHUNK)   // 128

// partials: [batch][chunk][5]  (main, diff, hsa, pauli, ghost)
__device__ float g_part[NB * NCHUNK * 5];
__device__ unsigned g_count = 0;

__global__ __launch_bounds__(NL) void pe_fused_kernel(
    const float* __restrict__ pos_L, const float* __restrict__ pos_P,
    const float* __restrict__ q_L,   const float* __restrict__ q_P,
    const float* __restrict__ x_L,   const float* __restrict__ x_P,
    const float* __restrict__ vdw_radii, const float* __restrict__ epsilon,
    float* __restrict__ out)
{
    const int c = blockIdx.x;            // protein chunk
    const int b = blockIdx.y;            // batch
    const int l = threadIdx.x;           // ligand index

    // ---- per-ligand derived quantities ----
    const float* xl = x_L + ((size_t)b * NL + l) * 9;
    float radL = 0.f, epsd = 0.f;
#pragma unroll
    for (int k = 0; k < 9; k++) {
        float x = xl[k];
        radL = fmaf(x, vdw_radii[k], radL);
        epsd = fmaf(x, epsilon[k],   epsd);
    }
    epsd = fmaxf(epsd, 0.f);
    const float c4   = 4.f * sqrtf(fmaf(epsd, 0.15f, 1e-8f));  // 4*eps_ij
    const float lx   = pos_L[((size_t)b * NL + l) * 3 + 0];
    const float ly   = pos_L[((size_t)b * NL + l) * 3 + 1];
    const float lz   = pos_L[((size_t)b * NL + l) * 3 + 2];
    const float ql83 = 83.015f * q_L[b * NL + l];              // 332.06/4 * q_L
    const float xl0  = xl[0];

    // ---- stage protein chunk into SMEM (packed) ----
    __shared__ float4 sp[CHUNK];   // x, y, z, q
    __shared__ float2 sr[CHUNK];   // radius, x0
    if (threadIdx.x < CHUNK) {
        const int p = c * CHUNK + threadIdx.x;
        const float4 xp = *(const float4*)(x_P + ((size_t)b * NP + p) * 4);
        float4 v;
        v.x = pos_P[((size_t)b * NP + p) * 3 + 0];
        v.y = pos_P[((size_t)b * NP + p) * 3 + 1];
        v.z = pos_P[((size_t)b * NP + p) * 3 + 2];
        v.w = q_P[b * NP + p];
        sp[threadIdx.x] = v;
        float2 r;
        r.x = fmaf(xp.x, 1.7f, fmaf(xp.y, 1.55f, fmaf(xp.z, 1.52f, xp.w * 1.8f)));
        r.y = xp.x;
        sr[threadIdx.x] = r;
    }
    __syncthreads();

    float s_main = 0.f, s_diff = 0.f, s_hsa = 0.f, s_pauli = 0.f, s_ghost = 0.f;

#pragma unroll 4
    for (int j = 0; j < CHUNK; j++) {
        const float4 p = sp[j];
        const float dx = lx - p.x;
        const float dy = ly - p.y;
        const float dz = lz - p.z;
        const float dsq = fmaf(dx, dx, fmaf(dy, dy, dz * dz));
        // Warp-coherent far cutoff: beyond 26 A every term is < 1e-11.
        if (__any_sync(0xffffffffu, dsq < 676.f)) {
            const float2 r = sr[j];
            const float t    = dsq + 1e-8f;
            const float invd = rsqrtf(t);
            const float dist = t * invd;                  // sqrt(dsq + 1e-8)

            const float sigma = radL + r.x;
            const float ssq   = fmaf(sigma, sigma, t);
            const float invs  = rsqrtf(ssq);              // 1/soft_dist

            const float e_elec = ql83 * p.w * invs;

            // ratio = sigma/soft_dist <= 1 always
            const float ratio = sigma * invs;
            const float r2 = ratio * ratio;
            const float r6 = r2 * r2 * r2;
            const float evr = c4 * fmaf(r6, r6, -r6);     // e_vdw_raw in [-0.52, 0]
            // softplus(evr+10)-10 = evr + exp(-(evr+10)) (log1p linearization, err<1e-9)
            const float ex = __expf(-(evr + 10.f));

            const float em = __expf(fmaf(2.f, dist, -24.f));   // mask = 1/(1+em)

            // hsa_term = 1/A with A = 1+(d/4)^4; single RCP for both:
            // R = 1/((1+em)*A) = hsa*mask ; mask = R*A
            const float dq = dist * 0.25f;
            const float d2 = dq * dq;
            const float A  = fmaf(d2, d2, 1.f);
            const float R  = __fdividef(1.f, A * (1.f + em));
            const float mask = R * A;

            s_main = fmaf(e_elec + evr + ex, mask, s_main);
            s_diff = fmaf(ex, mask, s_diff);
            s_hsa  = fmaf(xl0 * r.y, R, s_hsa);

            const float ov = fmaxf(fmaf(sigma, 0.6f, -dist), 0.f);
            s_pauli = fmaf(ov, ov, s_pauli);
            const float gh = fmaxf(0.5f - dist, 0.f);
            s_ghost = fmaf(gh, gh, s_ghost);
        }
    }

    // ---- deterministic block reduction ----
    float v[5] = {s_main, s_diff, s_hsa, s_pauli, s_ghost};
#pragma unroll
    for (int k = 0; k < 5; k++) {
#pragma unroll
        for (int off = 16; off > 0; off >>= 1)
            v[k] += __shfl_down_sync(0xffffffffu, v[k], off);
    }
    __shared__ float wred[4][5];
    const int wid = threadIdx.x >> 5, lane = threadIdx.x & 31;
    if (lane == 0) {
#pragma unroll
        for (int k = 0; k < 5; k++) wred[wid][k] = v[k];
    }
    __syncthreads();
    if (threadIdx.x == 0) {
#pragma unroll
        for (int k = 0; k < 5; k++)
            g_part[(b * NCHUNK + c) * 5 + k] =
                wred[0][k] + wred[1][k] + wred[2][k] + wred[3][k];
    }

    // ---- last block finalizes (threadfence reduction pattern) ----
    __shared__ bool is_last;
    if (threadIdx.x == 0) {
        __threadfence();
        unsigned done = atomicAdd(&g_count, 1u);
        is_last = (done == (unsigned)(gridDim.x * gridDim.y) - 1u);
    }
    __syncthreads();
    if (!is_last) return;

    __shared__ float acc[NB][5];
    for (int task = wid; task < NB * 5; task += 4) {
        const int tb = task / 5, tk = task % 5;
        float s = 0.f;
#pragma unroll
        for (int cc = lane; cc < NCHUNK; cc += 32)
            s += g_part[(tb * NCHUNK + cc) * 5 + tk];
#pragma unroll
        for (int off = 16; off > 0; off >>= 1)
            s += __shfl_down_sync(0xffffffffu, s, off);
        if (lane == 0) acc[tb][tk] = s;
    }
    __syncthreads();
    if (threadIdx.x < NB) {
        const int w = threadIdx.x;
        const float s_m = acc[w][0], s_d = acc[w][1], s_h = acc[w][2],
                    s_p = acc[w][3], s_g = acc[w][4];
        const float e_hsa5  = -2.5f * s_h;                    // 5 * (-0.5 * s_hsa)
        const float e_pauli = 11.920292202211755f * s_p;      // 100*sigmoid(-2)
        const float e_ghost = 500.f * s_g;

        out[w] = s_m + e_hsa5 + e_pauli + e_ghost;            // e_raw

        const float e_hard = fminf(e_pauli + e_ghost, 10000.f);
        out[8 + w] = e_hard;

        float log_soft = (s_m - s_d) + e_hsa5;
        float e_soft_final = fminf(fmaxf(log_soft, -500.f), 5000.f);
        out[16 + w] = fminf(e_soft_final + e_hard, 1000000.f);
    }
    if (threadIdx.x == 0) g_count = 0;   // reset for next graph replay
}

extern "C" void kernel_launch(void* const* d_in, const int* in_sizes, int n_in,
                              void* d_out, int out_size)
{
    const float* pos_L = (const float*)d_in[0];
    const float* pos_P = (const float*)d_in[1];
    const float* q_L   = (const float*)d_in[2];
    const float* q_P   = (const float*)d_in[3];
    const float* x_L   = (const float*)d_in[4];
    const float* x_P   = (const float*)d_in[5];
    const float* vdw   = (const float*)d_in[6];
    const float* eps   = (const float*)d_in[7];

    dim3 grid(NCHUNK, NB);
    pe_fused_kernel<<<grid, NL>>>(pos_L, pos_P, q_L, q_P, x_L, x_P, vdw, eps,
                                  (float*)d_out);
}

// round 3
// speedup vs baseline: 1.1006x; 1.1006x over previous
#include <cuda_runtime.h>

// PhysicsEngine: B=8, NL=128, NP=8192 pairwise soft-core energy -> 3 scalars/batch.
// Single fused kernel: grid (256 chunks, 8 batches) x 128 threads (thread = ligand),
// 32 SMEM-staged protein atoms per chunk, branch-free unrolled inner loop.
// Last block (threadfence + atomic counter) reduces partials and writes 24 outputs.

#define NB 8
#define NL 128
#define NP 8192
#define CHUNK 32
#define NCHUNK (NP / CHUNK)   // 256

// partials: [batch][chunk][5]  (main, diff, hsa, pauli, ghost)
__device__ float g_part[NB * NCHUNK * 5];
__device__ unsigned g_count = 0;

__global__ __launch_bounds__(NL, 12) void pe_fused_kernel(
    const float* __restrict__ pos_L, const float* __restrict__ pos_P,
    const float* __restrict__ q_L,   const float* __restrict__ q_P,
    const float* __restrict__ x_L,   const float* __restrict__ x_P,
    const float* __restrict__ vdw_radii, const float* __restrict__ epsilon,
    float* __restrict__ out)
{
    const int c = blockIdx.x;            // protein chunk
    const int b = blockIdx.y;            // batch
    const int l = threadIdx.x;           // ligand index

    // ---- stage protein chunk into SMEM (packed) ----
    __shared__ float4 sp[CHUNK];   // x, y, z, q
    __shared__ float2 sr[CHUNK];   // radius, x0
    if (threadIdx.x < CHUNK) {
        const int p = c * CHUNK + threadIdx.x;
        const float4 xp = *(const float4*)(x_P + ((size_t)b * NP + p) * 4);
        float4 v;
        v.x = pos_P[((size_t)b * NP + p) * 3 + 0];
        v.y = pos_P[((size_t)b * NP + p) * 3 + 1];
        v.z = pos_P[((size_t)b * NP + p) * 3 + 2];
        v.w = q_P[b * NP + p];
        sp[threadIdx.x] = v;
        float2 r;
        r.x = fmaf(xp.x, 1.7f, fmaf(xp.y, 1.55f, fmaf(xp.z, 1.52f, xp.w * 1.8f)));
        r.y = xp.x;
        sr[threadIdx.x] = r;
    }

    // ---- per-ligand derived quantities ----
    const float* xl = x_L + ((size_t)b * NL + l) * 9;
    float radL = 0.f, epsd = 0.f;
#pragma unroll
    for (int k = 0; k < 9; k++) {
        float x = xl[k];
        radL = fmaf(x, vdw_radii[k], radL);
        epsd = fmaf(x, epsilon[k],   epsd);
    }
    epsd = fmaxf(epsd, 0.f);
    const float c4   = 4.f * sqrtf(fmaf(epsd, 0.15f, 1e-8f));  // 4*eps_ij
    const float lx   = pos_L[((size_t)b * NL + l) * 3 + 0];
    const float ly   = pos_L[((size_t)b * NL + l) * 3 + 1];
    const float lz   = pos_L[((size_t)b * NL + l) * 3 + 2];
    const float ql83 = 83.015f * q_L[b * NL + l];              // 332.06/4 * q_L
    const float xl0  = xl[0];

    __syncthreads();

    float s_main = 0.f, s_diff = 0.f, s_hsa = 0.f, s_pauli = 0.f, s_ghost = 0.f;

#pragma unroll 8
    for (int j = 0; j < CHUNK; j++) {
        const float4 p = sp[j];
        const float2 r = sr[j];
        const float dx = lx - p.x;
        const float dy = ly - p.y;
        const float dz = lz - p.z;
        const float dsq = fmaf(dx, dx, fmaf(dy, dy, dz * dz));

        const float t    = dsq + 1e-8f;
        const float invd = rsqrtf(t);
        const float dist = t * invd;                  // sqrt(dsq + 1e-8)

        const float sigma = radL + r.x;
        const float ssq   = fmaf(sigma, sigma, t);
        const float invs  = rsqrtf(ssq);              // 1/soft_dist

        const float e_elec = ql83 * p.w * invs;

        // ratio = sigma/soft_dist <= 1 always (min(.,5) never binds)
        const float ratio = sigma * invs;
        const float r2 = ratio * ratio;
        const float r6 = r2 * r2 * r2;
        const float evr = c4 * fmaf(r6, r6, -r6);     // e_vdw_raw in [-0.52, 0]
        // softplus(evr+10)-10 = evr + exp(-(evr+10)) (log1p linearization, err<1e-9)
        const float ex = exp2f(fmaf(evr, -1.442695041f, -14.42695041f));
        // em = exp(2*dist - 24); mask = 1/(1+em)
        const float em = exp2f(fmaf(dist, 2.885390082f, -34.63068049f));

        // hsa_term = 1/A with A = 1 + (d/4)^4 = 1 + dsq^2/256 (no dist dependency)
        const float A  = fmaf(dsq * dsq, 0.00390625f, 1.f);
        // single RCP serves both: R = 1/((1+em)*A) = hsa*mask ; mask = R*A
        const float R    = __fdividef(1.f, A * (1.f + em));
        const float mask = R * A;

        s_main = fmaf(e_elec + evr + ex, mask, s_main);
        s_diff = fmaf(ex, mask, s_diff);
        s_hsa  = fmaf(xl0 * r.y, R, s_hsa);

        const float ov = fmaxf(fmaf(sigma, 0.6f, -dist), 0.f);
        s_pauli = fmaf(ov, ov, s_pauli);
        const float gh = fmaxf(0.5f - dist, 0.f);
        s_ghost = fmaf(gh, gh, s_ghost);
    }

    // ---- deterministic block reduction ----
    float v[5] = {s_main, s_diff, s_hsa, s_pauli, s_ghost};
#pragma unroll
    for (int k = 0; k < 5; k++) {
#pragma unroll
        for (int off = 16; off > 0; off >>= 1)
            v[k] += __shfl_down_sync(0xffffffffu, v[k], off);
    }
    __shared__ float wred[4][5];
    const int wid = threadIdx.x >> 5, lane = threadIdx.x & 31;
    if (lane == 0) {
#pragma unroll
        for (int k = 0; k < 5; k++) wred[wid][k] = v[k];
    }
    __syncthreads();
    if (threadIdx.x == 0) {
#pragma unroll
        for (int k = 0; k < 5; k++)
            g_part[(b * NCHUNK + c) * 5 + k] =
                wred[0][k] + wred[1][k] + wred[2][k] + wred[3][k];
    }

    // ---- last block finalizes (threadfence reduction pattern) ----
    __shared__ bool is_last;
    if (threadIdx.x == 0) {
        __threadfence();
        unsigned done = atomicAdd(&g_count, 1u);
        is_last = (done == (unsigned)(gridDim.x * gridDim.y) - 1u);
    }
    __syncthreads();
    if (!is_last) return;

    __shared__ float acc[NB][5];
    for (int task = wid; task < NB * 5; task += 4) {
        const int tb = task / 5, tk = task % 5;
        float s = 0.f;
#pragma unroll
        for (int cc = lane; cc < NCHUNK; cc += 32)
            s += g_part[(tb * NCHUNK + cc) * 5 + tk];
#pragma unroll
        for (int off = 16; off > 0; off >>= 1)
            s += __shfl_down_sync(0xffffffffu, s, off);
        if (lane == 0) acc[tb][tk] = s;
    }
    __syncthreads();
    if (threadIdx.x < NB) {
        const int w = threadIdx.x;
        const float s_m = acc[w][0], s_d = acc[w][1], s_h = acc[w][2],
                    s_p = acc[w][3], s_g = acc[w][4];
        const float e_hsa5  = -2.5f * s_h;                    // 5 * (-0.5 * s_hsa)
        const float e_pauli = 11.920292202211755f * s_p;      // 100*sigmoid(-2)
        const float e_ghost = 500.f * s_g;

        out[w] = s_m + e_hsa5 + e_pauli + e_ghost;            // e_raw

        const float e_hard = fminf(e_pauli + e_ghost, 10000.f);
        out[8 + w] = e_hard;

        float log_soft = (s_m - s_d) + e_hsa5;
        float e_soft_final = fminf(fmaxf(log_soft, -500.f), 5000.f);
        out[16 + w] = fminf(e_soft_final + e_hard, 1000000.f);
    }
    if (threadIdx.x == 0) g_count = 0;   // reset for next graph replay
}

extern "C" void kernel_launch(void* const* d_in, const int* in_sizes, int n_in,
                              void* d_out, int out_size)
{
    const float* pos_L = (const float*)d_in[0];
    const float* pos_P = (const float*)d_in[1];
    const float* q_L   = (const float*)d_in[2];
    const float* q_P   = (const float*)d_in[3];
    const float* x_L   = (const float*)d_in[4];
    const float* x_P   = (const float*)d_in[5];
    const float* vdw   = (const float*)d_in[6];
    const float* eps   = (const float*)d_in[7];

    dim3 grid(NCHUNK, NB);
    pe_fused_kernel<<<grid, NL>>>(pos_L, pos_P, q_L, q_P, x_L, x_P, vdw, eps,
                                  (float*)d_out);
}